// round 1
// baseline (speedup 1.0000x reference)
#include <cuda_runtime.h>

// SGU: out = (xh * (tril(W) @ LN(gate) + bias)) @ proj_w + proj_b
// x: (4096, 4096) [xh | gate], W: (4096,4096), proj_w: (2048,1024)

constexpr int SEQ  = 4096;
constexpr int DH   = 2048;
constexpr int DOUT = 1024;
constexpr int XW   = 2 * DH;  // 4096

// Scratch (device globals — no runtime allocation allowed)
__device__ float g_gate[(size_t)SEQ * DH];  // LayerNormed gate
__device__ float g_mix [(size_t)SEQ * DH];  // tril(W)@gate + bias

// ---------------------------------------------------------------------------
// Kernel 1: LayerNorm (scale only, eps=1e-5) over the gate half of x.
// One block (256 threads) per row of 2048 elements.
// ---------------------------------------------------------------------------
__global__ void __launch_bounds__(256) ln_kernel(const float* __restrict__ x,
                                                 const float* __restrict__ ln_scale) {
    int row = blockIdx.x;
    const float* g = x + (size_t)row * XW + DH;
    float* out = g_gate + (size_t)row * DH;
    int t = threadIdx.x;

    float vals[8];
    float sum = 0.f, sq = 0.f;
#pragma unroll
    for (int i = 0; i < 8; i++) {
        float v = g[t + i * 256];
        vals[i] = v;
        sum += v;
        sq  += v * v;
    }
#pragma unroll
    for (int o = 16; o; o >>= 1) {
        sum += __shfl_xor_sync(0xffffffffu, sum, o);
        sq  += __shfl_xor_sync(0xffffffffu, sq,  o);
    }
    __shared__ float ssum[8], ssq[8];
    __shared__ float s_mean, s_rstd;
    if ((t & 31) == 0) { ssum[t >> 5] = sum; ssq[t >> 5] = sq; }
    __syncthreads();
    if (t == 0) {
        float S = 0.f, Q = 0.f;
#pragma unroll
        for (int i = 0; i < 8; i++) { S += ssum[i]; Q += ssq[i]; }
        float mean = S * (1.f / DH);
        float var  = Q * (1.f / DH) - mean * mean;
        s_mean = mean;
        s_rstd = rsqrtf(var + 1e-5f);
    }
    __syncthreads();
    float mean = s_mean, rstd = s_rstd;
#pragma unroll
    for (int i = 0; i < 8; i++) {
        int c = t + i * 256;
        out[c] = (vals[i] - mean) * rstd * ln_scale[c];
    }
}

// ---------------------------------------------------------------------------
// Kernel 2: g_mix = tril(W) @ g_gate + bias
// C (SEQ x DH) = W (SEQ x SEQ, lower-tri) @ G (SEQ x DH)
// 128x128 block tile, BK=8, 256 threads, 8x8 register tile per thread.
// Triangular: K-loop truncated at end of this block's row range; only the
// diagonal K-block needs per-element masking (mask is applied always, cheap).
// ---------------------------------------------------------------------------
__global__ void __launch_bounds__(256) mix_kernel(const float* __restrict__ W,
                                                  const float* __restrict__ bias) {
    constexpr int BM = 128, BN = 128, BK = 8;
    __shared__ float As[BK][BM];  // W tile, transposed: As[k][m]
    __shared__ float Bs[BK][BN];

    int bx = blockIdx.x, by = blockIdx.y;
    int tid = threadIdx.x;
    int row0 = by * BM;
    int col0 = bx * BN;
    int kEnd = row0 + BM;  // causal: columns (K) beyond this row block are zero

    int tx = tid & 15;        // 0..15 -> N direction (8 cols each)
    int ty = tid >> 4;        // 0..15 -> M direction (8 rows each)

    // A tile load: 128 rows x 8 cols of W -> each thread one float4
    int a_row = tid >> 1;             // 0..127
    int a_col = (tid & 1) * 4;        // 0 or 4
    // B tile load: 8 rows x 128 cols of G -> each thread one float4
    int b_row = tid >> 5;             // 0..7
    int b_col = (tid & 31) * 4;       // 0..124

    float acc[8][8];
#pragma unroll
    for (int i = 0; i < 8; i++)
#pragma unroll
        for (int j = 0; j < 8; j++) acc[i][j] = 0.f;

    for (int k0 = 0; k0 < kEnd; k0 += BK) {
        int m = row0 + a_row;
        float4 av = *reinterpret_cast<const float4*>(W + (size_t)m * SEQ + k0 + a_col);
        // tril mask: W[m][n] valid iff n <= m
        int kg = k0 + a_col;
        As[a_col + 0][a_row] = (kg + 0 <= m) ? av.x : 0.f;
        As[a_col + 1][a_row] = (kg + 1 <= m) ? av.y : 0.f;
        As[a_col + 2][a_row] = (kg + 2 <= m) ? av.z : 0.f;
        As[a_col + 3][a_row] = (kg + 3 <= m) ? av.w : 0.f;

        float4 bv = *reinterpret_cast<const float4*>(g_gate + (size_t)(k0 + b_row) * DH + col0 + b_col);
        *reinterpret_cast<float4*>(&Bs[b_row][b_col]) = bv;
        __syncthreads();

#pragma unroll
        for (int k = 0; k < BK; k++) {
            float ar[8], br[8];
#pragma unroll
            for (int i = 0; i < 8; i++) ar[i] = As[k][ty * 8 + i];
#pragma unroll
            for (int j = 0; j < 8; j++) br[j] = Bs[k][tx * 8 + j];
#pragma unroll
            for (int i = 0; i < 8; i++)
#pragma unroll
                for (int j = 0; j < 8; j++) acc[i][j] += ar[i] * br[j];
        }
        __syncthreads();
    }

#pragma unroll
    for (int i = 0; i < 8; i++) {
        int row = row0 + ty * 8 + i;
        float b = bias[row];
        float* dst = g_mix + (size_t)row * DH + col0 + tx * 8;
#pragma unroll
        for (int j = 0; j < 8; j++) dst[j] = acc[i][j] + b;
    }
}

// ---------------------------------------------------------------------------
// Kernel 3: out = (xh * g_mix) @ proj_w + proj_b
// A[m,k] = x[m, k] * g_mix[m, k] computed on the fly during the A-tile load.
// M=4096, N=1024, K=2048. Same tiling as kernel 2.
// ---------------------------------------------------------------------------
__global__ void __launch_bounds__(256) proj_kernel(const float* __restrict__ x,
                                                   const float* __restrict__ P,
                                                   const float* __restrict__ pb,
                                                   float* __restrict__ out) {
    constexpr int BM = 128, BN = 128, BK = 8;
    __shared__ float As[BK][BM];
    __shared__ float Bs[BK][BN];

    int bx = blockIdx.x, by = blockIdx.y;
    int tid = threadIdx.x;
    int row0 = by * BM;
    int col0 = bx * BN;

    int tx = tid & 15;
    int ty = tid >> 4;

    int a_row = tid >> 1;
    int a_col = (tid & 1) * 4;
    int b_row = tid >> 5;
    int b_col = (tid & 31) * 4;

    float acc[8][8];
#pragma unroll
    for (int i = 0; i < 8; i++)
#pragma unroll
        for (int j = 0; j < 8; j++) acc[i][j] = 0.f;

    for (int k0 = 0; k0 < DH; k0 += BK) {
        int m = row0 + a_row;
        float4 xv = *reinterpret_cast<const float4*>(x + (size_t)m * XW + k0 + a_col);
        float4 gv = *reinterpret_cast<const float4*>(g_mix + (size_t)m * DH + k0 + a_col);
        As[a_col + 0][a_row] = xv.x * gv.x;
        As[a_col + 1][a_row] = xv.y * gv.y;
        As[a_col + 2][a_row] = xv.z * gv.z;
        As[a_col + 3][a_row] = xv.w * gv.w;

        float4 bv = *reinterpret_cast<const float4*>(P + (size_t)(k0 + b_row) * DOUT + col0 + b_col);
        *reinterpret_cast<float4*>(&Bs[b_row][b_col]) = bv;
        __syncthreads();

#pragma unroll
        for (int k = 0; k < BK; k++) {
            float ar[8], br[8];
#pragma unroll
            for (int i = 0; i < 8; i++) ar[i] = As[k][ty * 8 + i];
#pragma unroll
            for (int j = 0; j < 8; j++) br[j] = Bs[k][tx * 8 + j];
#pragma unroll
            for (int i = 0; i < 8; i++)
#pragma unroll
                for (int j = 0; j < 8; j++) acc[i][j] += ar[i] * br[j];
        }
        __syncthreads();
    }

#pragma unroll
    for (int i = 0; i < 8; i++) {
        int row = row0 + ty * 8 + i;
        float* dst = out + (size_t)row * DOUT + col0 + tx * 8;
#pragma unroll
        for (int j = 0; j < 8; j++) dst[j] = acc[i][j] + pb[col0 + tx * 8 + j];
    }
}

// ---------------------------------------------------------------------------
// Launch. Inputs (metadata order): x, ln_scale, spatial_weights,
// spatial_biases, proj_w, proj_b. Output fp32 (4096, 1024).
// ---------------------------------------------------------------------------
extern "C" void kernel_launch(void* const* d_in, const int* in_sizes, int n_in,
                              void* d_out, int out_size) {
    const float* x    = (const float*)d_in[0];
    const float* lns  = (const float*)d_in[1];
    const float* W    = (const float*)d_in[2];
    const float* sb   = (const float*)d_in[3];
    const float* pw   = (const float*)d_in[4];
    const float* pb   = (const float*)d_in[5];
    float* out = (float*)d_out;

    ln_kernel<<<SEQ, 256>>>(x, lns);

    dim3 gmix(DH / 128, SEQ / 128);   // (16, 32)
    mix_kernel<<<gmix, 256>>>(W, sb);

    dim3 gproj(DOUT / 128, SEQ / 128); // (8, 32)
    proj_kernel<<<gproj, 256>>>(x, pw, pb, out);
}